// round 3
// baseline (speedup 1.0000x reference)
#include <cuda_runtime.h>
#include <cstddef>

#define N_NODES 50000
#define N_EDGES 800000
#define DIM 96
#define EDIM 32
#define BN_EPS 1e-5f

// Scratch (alloc-free rule: __device__ globals). float4 for alignment.
__device__ float4 g_aggr[N_NODES * DIM / 4];
__device__ float4 g_h1[N_NODES * DIM / 4];
__device__ float4 g_h2[N_NODES * DIM / 4];
__device__ float g_sum[DIM];
__device__ float g_sumsq[DIM];
__device__ float g_scale[DIM];
__device__ float g_shift[DIM];

// ---------------------------------------------------------------------------
// Kernel A: zero aggr + BN accumulators
// ---------------------------------------------------------------------------
__global__ void zero_kernel() {
    int i = blockIdx.x * blockDim.x + threadIdx.x;
    int stride = gridDim.x * blockDim.x;
    const float4 z4 = make_float4(0.f, 0.f, 0.f, 0.f);
    for (int j = i; j < N_NODES * DIM / 4; j += stride) g_aggr[j] = z4;
    if (i < DIM) { g_sum[i] = 0.f; g_sumsq[i] = 0.f; }
}

// ---------------------------------------------------------------------------
// Kernel B: per-edge  msg = relu(x[src] + ea@We + be); aggr[dst] += msg
// warp-per-edge, We register-resident (3 output dims per lane)
// ---------------------------------------------------------------------------
__global__ void __launch_bounds__(256) edge_kernel(
    const float* __restrict__ x,
    const int* __restrict__ ei,          // [2, E] int32, row0=src, row1=dst
    const float* __restrict__ ea,        // [E, 32]
    const float* __restrict__ We,        // [32, 96]
    const float* __restrict__ be)        // [96]
{
    const int lane = threadIdx.x & 31;
    const int warp = (blockIdx.x * blockDim.x + threadIdx.x) >> 5;
    const int nwarps = (gridDim.x * blockDim.x) >> 5;

    // Register-resident weight columns for this lane's 3 output dims
    float w0[EDIM], w1[EDIM], w2[EDIM];
#pragma unroll
    for (int k = 0; k < EDIM; k++) {
        w0[k] = We[k * DIM + lane];
        w1[k] = We[k * DIM + lane + 32];
        w2[k] = We[k * DIM + lane + 64];
    }
    const float bb0 = be[lane], bb1 = be[lane + 32], bb2 = be[lane + 64];
    float* aggr = reinterpret_cast<float*>(g_aggr);

    for (int e = warp; e < N_EDGES; e += nwarps) {
        int src = ei[e];
        int dst = ei[N_EDGES + e];
        float eav = ea[(size_t)e * EDIM + lane];   // lane k holds ea[e][k]

        float a0 = bb0, a1 = bb1, a2 = bb2;
#pragma unroll
        for (int k = 0; k < EDIM; k++) {
            float v = __shfl_sync(0xffffffffu, eav, k);
            a0 += v * w0[k];
            a1 += v * w1[k];
            a2 += v * w2[k];
        }
        const float* xr = x + (size_t)src * DIM;
        a0 = fmaxf(a0 + xr[lane], 0.f);
        a1 = fmaxf(a1 + xr[lane + 32], 0.f);
        a2 = fmaxf(a2 + xr[lane + 64], 0.f);

        float* ar = aggr + (size_t)dst * DIM;
        atomicAdd(ar + lane, a0);
        atomicAdd(ar + lane + 32, a1);
        atomicAdd(ar + lane + 64, a2);
    }
}

// ---------------------------------------------------------------------------
// Kernel C1: h1 = relu((x + aggr) @ W1 + b1)
// warp handles 4 nodes, 3 output dims per lane, W1 in shared
// ---------------------------------------------------------------------------
__global__ void __launch_bounds__(256) mlp1_kernel(
    const float* __restrict__ x,
    const float* __restrict__ W1,
    const float* __restrict__ b1)
{
    __shared__ float sW[DIM * DIM];
    __shared__ float sb[DIM];
    const int tid = threadIdx.x;
    for (int i = tid; i < DIM * DIM; i += 256) sW[i] = W1[i];
    if (tid < DIM) sb[tid] = b1[tid];
    __syncthreads();

    const int lane = tid & 31;
    const int warp = tid >> 5;
    const int n0 = (blockIdx.x * 8 + warp) * 4;
    const float* aggr = reinterpret_cast<const float*>(g_aggr);
    float* h1 = reinterpret_cast<float*>(g_h1);

    float u[4][3];
#pragma unroll
    for (int j = 0; j < 4; j++) {
        int n = n0 + j;
        if (n < N_NODES) {
#pragma unroll
            for (int i = 0; i < 3; i++) {
                int idx = n * DIM + lane + 32 * i;
                u[j][i] = x[idx] + aggr[idx];
            }
        } else {
            u[j][0] = u[j][1] = u[j][2] = 0.f;
        }
    }

    float a[4][3];
#pragma unroll
    for (int j = 0; j < 4; j++)
#pragma unroll
        for (int i = 0; i < 3; i++) a[j][i] = sb[lane + 32 * i];

#pragma unroll
    for (int i = 0; i < 3; i++) {
#pragma unroll
        for (int kk = 0; kk < 32; kk++) {
            const int k = i * 32 + kk;
            const float wv0 = sW[k * DIM + lane];
            const float wv1 = sW[k * DIM + lane + 32];
            const float wv2 = sW[k * DIM + lane + 64];
#pragma unroll
            for (int j = 0; j < 4; j++) {
                float v = __shfl_sync(0xffffffffu, u[j][i], kk);
                a[j][0] += v * wv0;
                a[j][1] += v * wv1;
                a[j][2] += v * wv2;
            }
        }
    }

#pragma unroll
    for (int j = 0; j < 4; j++) {
        int n = n0 + j;
        if (n < N_NODES) {
#pragma unroll
            for (int i = 0; i < 3; i++)
                h1[n * DIM + lane + 32 * i] = fmaxf(a[j][i], 0.f);
        }
    }
}

// ---------------------------------------------------------------------------
// Kernel C2: h2 = h1 @ W2 + b2, plus BN partial sums (sum, sumsq per feature)
// ---------------------------------------------------------------------------
__global__ void __launch_bounds__(256) mlp2_kernel(
    const float* __restrict__ W2,
    const float* __restrict__ b2)
{
    __shared__ float sW[DIM * DIM];
    __shared__ float sb[DIM];
    __shared__ float sSum[DIM];
    __shared__ float sSq[DIM];
    const int tid = threadIdx.x;
    for (int i = tid; i < DIM * DIM; i += 256) sW[i] = W2[i];
    if (tid < DIM) { sb[tid] = b2[tid]; sSum[tid] = 0.f; sSq[tid] = 0.f; }
    __syncthreads();

    const int lane = tid & 31;
    const int warp = tid >> 5;
    const int n0 = (blockIdx.x * 8 + warp) * 4;
    const float* h1 = reinterpret_cast<const float*>(g_h1);
    float* h2 = reinterpret_cast<float*>(g_h2);

    float u[4][3];
#pragma unroll
    for (int j = 0; j < 4; j++) {
        int n = n0 + j;
        if (n < N_NODES) {
#pragma unroll
            for (int i = 0; i < 3; i++)
                u[j][i] = h1[n * DIM + lane + 32 * i];
        } else {
            u[j][0] = u[j][1] = u[j][2] = 0.f;
        }
    }

    float a[4][3];
#pragma unroll
    for (int j = 0; j < 4; j++)
#pragma unroll
        for (int i = 0; i < 3; i++) a[j][i] = sb[lane + 32 * i];

#pragma unroll
    for (int i = 0; i < 3; i++) {
#pragma unroll
        for (int kk = 0; kk < 32; kk++) {
            const int k = i * 32 + kk;
            const float wv0 = sW[k * DIM + lane];
            const float wv1 = sW[k * DIM + lane + 32];
            const float wv2 = sW[k * DIM + lane + 64];
#pragma unroll
            for (int j = 0; j < 4; j++) {
                float v = __shfl_sync(0xffffffffu, u[j][i], kk);
                a[j][0] += v * wv0;
                a[j][1] += v * wv1;
                a[j][2] += v * wv2;
            }
        }
    }

    float ps[3] = {0.f, 0.f, 0.f};
    float pq[3] = {0.f, 0.f, 0.f};
#pragma unroll
    for (int j = 0; j < 4; j++) {
        int n = n0 + j;
        if (n < N_NODES) {
#pragma unroll
            for (int i = 0; i < 3; i++) {
                float v = a[j][i];
                h2[n * DIM + lane + 32 * i] = v;
                ps[i] += v;
                pq[i] += v * v;
            }
        }
    }
#pragma unroll
    for (int i = 0; i < 3; i++) {
        atomicAdd(&sSum[lane + 32 * i], ps[i]);
        atomicAdd(&sSq[lane + 32 * i], pq[i]);
    }
    __syncthreads();
    if (tid < DIM) {
        atomicAdd(&g_sum[tid], sSum[tid]);
        atomicAdd(&g_sumsq[tid], sSq[tid]);
    }
}

// ---------------------------------------------------------------------------
// Kernel D: BN scale/shift from accumulated stats (1 block, 96 threads)
// ---------------------------------------------------------------------------
__global__ void bnstat_kernel(const float* __restrict__ gamma,
                              const float* __restrict__ beta)
{
    int f = threadIdx.x;
    if (f < DIM) {
        float mean = g_sum[f] * (1.f / N_NODES);
        float var = g_sumsq[f] * (1.f / N_NODES) - mean * mean;
        float sc = gamma[f] * rsqrtf(var + BN_EPS);
        g_scale[f] = sc;
        g_shift[f] = beta[f] - mean * sc;
    }
}

// ---------------------------------------------------------------------------
// Kernel E: out = relu(h2 * scale + shift)
// ---------------------------------------------------------------------------
__global__ void bn_apply_kernel(float* __restrict__ out)
{
    int i = blockIdx.x * blockDim.x + threadIdx.x;
    int stride = gridDim.x * blockDim.x;
    const int tot4 = N_NODES * DIM / 4;
    float4* out4 = reinterpret_cast<float4*>(out);
    for (int j = i; j < tot4; j += stride) {
        float4 v = g_h2[j];
        int f = (j * 4) % DIM;   // DIM % 4 == 0 -> no wrap inside a float4
        v.x = fmaxf(v.x * g_scale[f + 0] + g_shift[f + 0], 0.f);
        v.y = fmaxf(v.y * g_scale[f + 1] + g_shift[f + 1], 0.f);
        v.z = fmaxf(v.z * g_scale[f + 2] + g_shift[f + 2], 0.f);
        v.w = fmaxf(v.w * g_scale[f + 3] + g_shift[f + 3], 0.f);
        out4[j] = v;
    }
}

// ---------------------------------------------------------------------------
extern "C" void kernel_launch(void* const* d_in, const int* in_sizes, int n_in,
                              void* d_out, int out_size)
{
    const float* x        = (const float*)d_in[0];
    const int* ei         = (const int*)d_in[1];
    const float* ea       = (const float*)d_in[2];
    const float* We       = (const float*)d_in[3];
    const float* be       = (const float*)d_in[4];
    const float* W1       = (const float*)d_in[5];
    const float* b1       = (const float*)d_in[6];
    const float* W2       = (const float*)d_in[7];
    const float* b2       = (const float*)d_in[8];
    const float* gamma    = (const float*)d_in[9];
    const float* beta     = (const float*)d_in[10];
    float* out            = (float*)d_out;

    zero_kernel<<<1184, 256>>>();
    edge_kernel<<<592, 256>>>(x, ei, ea, We, be);
    {
        const int nblocks = (N_NODES + 31) / 32;  // 32 nodes per block
        mlp1_kernel<<<nblocks, 256>>>(x, W1, b1);
        mlp2_kernel<<<nblocks, 256>>>(W2, b2);
    }
    bnstat_kernel<<<1, 128>>>(gamma, beta);
    bn_apply_kernel<<<1184, 256>>>(out);
}

// round 5
// speedup vs baseline: 2.1730x; 2.1730x over previous
#include <cuda_runtime.h>
#include <cstddef>

#define N_NODES 50000
#define N_EDGES 800000
#define DIM 96
#define EDIM 32
#define BN_EPS 1e-5f

typedef unsigned long long u64;

// Scratch (__device__ globals per alloc-free rule)
__device__ float4 g_aggr[N_NODES * DIM / 4];
__device__ float4 g_h1[N_NODES * DIM / 4];
__device__ float4 g_h2[N_NODES * DIM / 4];
__device__ float g_sum[DIM];
__device__ float g_sumsq[DIM];
__device__ float g_scale[DIM];
__device__ float g_shift[DIM];

// ---- Blackwell packed f32x2 helpers -------------------------------------
__device__ __forceinline__ u64 fma2(u64 a, u64 b, u64 c) {
    u64 d;
    asm("fma.rn.f32x2 %0, %1, %2, %3;" : "=l"(d) : "l"(a), "l"(b), "l"(c));
    return d;
}
__device__ __forceinline__ u64 pack1(float x) {
    u64 r;
    asm("mov.b64 %0, {%1, %1};" : "=l"(r) : "f"(x));
    return r;
}
__device__ __forceinline__ u64 pack2f(float a, float b) {
    u64 r;
    asm("mov.b64 %0, {%1, %2};" : "=l"(r) : "f"(a), "f"(b));
    return r;
}
__device__ __forceinline__ void unpack2(u64 v, float& a, float& b) {
    asm("mov.b64 {%0, %1}, %2;" : "=f"(a), "=f"(b) : "l"(v));
}
// vectorized global reduction: 4 fp32 adds in one L2 op (sm_90+)
__device__ __forceinline__ void red4(float* p, float a, float b, float c, float d) {
    asm volatile("red.global.add.v4.f32 [%0], {%1, %2, %3, %4};"
                 :: "l"(p), "f"(a), "f"(b), "f"(c), "f"(d) : "memory");
}

// ---------------------------------------------------------------------------
// Kernel A: zero aggr + BN accumulators
// ---------------------------------------------------------------------------
__global__ void zero_kernel() {
    int i = blockIdx.x * blockDim.x + threadIdx.x;
    int stride = gridDim.x * blockDim.x;
    const float4 z4 = make_float4(0.f, 0.f, 0.f, 0.f);
    for (int j = i; j < N_NODES * DIM / 4; j += stride) g_aggr[j] = z4;
    if (i < DIM) { g_sum[i] = 0.f; g_sumsq[i] = 0.f; }
}

// ---------------------------------------------------------------------------
// Kernel B: fused edge GEMM + scatter.
// Block = 128 edges. 256 threads as 32 rows (4 edges each) x 8 cols (12 outs).
// proj = ea @ We + be computed in registers (f32x2), epilogue does
// relu(x[src] + proj) and red.v4 into aggr[dst]. 800000 = 6250*128 exactly.
// ---------------------------------------------------------------------------
__global__ void __launch_bounds__(256) edge_kernel(
    const float* __restrict__ x,
    const int* __restrict__ ei,        // [2, E]: row0=src, row1=dst
    const float* __restrict__ ea,      // [E, 32]
    const float* __restrict__ We,      // [32, 96]
    const float* __restrict__ be)      // [96]
{
    __shared__ __align__(16) float ea_s[128 * 32];
    __shared__ __align__(16) float we_s[32 * 96];
    __shared__ __align__(16) float be_s[96];
    __shared__ int src_s[128];
    __shared__ int dst_s[128];

    const int tid = threadIdx.x;
    const int r = tid >> 3;      // 0..31 : edge group (4 edges)
    const int c = tid & 7;       // 0..7  : output group (12 outs)
    const int e0 = blockIdx.x * 128;

    // loads (all coalesced float4)
    {
        const float4* eag = reinterpret_cast<const float4*>(ea) + (size_t)e0 * 8;
        float4* eas = reinterpret_cast<float4*>(ea_s);
#pragma unroll
        for (int j = 0; j < 4; j++) eas[tid + 256 * j] = eag[tid + 256 * j];
        const float4* wg = reinterpret_cast<const float4*>(We);
        float4* ws = reinterpret_cast<float4*>(we_s);
#pragma unroll
        for (int j = 0; j < 3; j++) ws[tid + 256 * j] = wg[tid + 256 * j];
        if (tid < 96) be_s[tid] = be[tid];
        if (tid < 128) { src_s[tid] = ei[e0 + tid]; dst_s[tid] = ei[N_EDGES + e0 + tid]; }
    }
    __syncthreads();

    u64 acc[4][6];
    {
        const u64* bp = reinterpret_cast<const u64*>(be_s + 12 * c);
#pragma unroll
        for (int j = 0; j < 4; j++)
#pragma unroll
            for (int i = 0; i < 6; i++) acc[j][i] = bp[i];
    }

#pragma unroll 8
    for (int k = 0; k < EDIM; k++) {
        const ulonglong2* wp = reinterpret_cast<const ulonglong2*>(we_s + k * 96 + 12 * c);
        ulonglong2 q0 = wp[0], q1 = wp[1], q2 = wp[2];
#pragma unroll
        for (int j = 0; j < 4; j++) {
            u64 u = pack1(ea_s[(r * 4 + j) * 32 + k]);
            acc[j][0] = fma2(q0.x, u, acc[j][0]);
            acc[j][1] = fma2(q0.y, u, acc[j][1]);
            acc[j][2] = fma2(q1.x, u, acc[j][2]);
            acc[j][3] = fma2(q1.y, u, acc[j][3]);
            acc[j][4] = fma2(q2.x, u, acc[j][4]);
            acc[j][5] = fma2(q2.y, u, acc[j][5]);
        }
    }

    // epilogue: relu(x[src] + proj), vectorized atomic scatter
    float* aggr = reinterpret_cast<float*>(g_aggr);
#pragma unroll
    for (int j = 0; j < 4; j++) {
        int el = r * 4 + j;
        int s = src_s[el], dv = dst_s[el];
        const float4* xr = reinterpret_cast<const float4*>(x + (size_t)s * DIM + 12 * c);
        float* ar = aggr + (size_t)dv * DIM + 12 * c;
#pragma unroll
        for (int i = 0; i < 3; i++) {
            float4 xv = xr[i];
            float a0, a1, a2, a3;
            unpack2(acc[j][2 * i], a0, a1);
            unpack2(acc[j][2 * i + 1], a2, a3);
            a0 = fmaxf(a0 + xv.x, 0.f);
            a1 = fmaxf(a1 + xv.y, 0.f);
            a2 = fmaxf(a2 + xv.z, 0.f);
            a3 = fmaxf(a3 + xv.w, 0.f);
            red4(ar + 4 * i, a0, a1, a2, a3);
        }
    }
}

// ---------------------------------------------------------------------------
// Kernel C1: h1 = relu((x + aggr) @ W1 + b1)
// Block = 128 nodes, 256 threads (32 rows x 8 cols), k chunked by 32.
// ---------------------------------------------------------------------------
__global__ void __launch_bounds__(256) mlp1_kernel(
    const float* __restrict__ x,
    const float* __restrict__ W1,
    const float* __restrict__ b1)
{
    __shared__ __align__(16) float u_s[128 * 32];
    __shared__ __align__(16) float w_s[32 * 96];
    const int tid = threadIdx.x;
    const int r = tid >> 3, c = tid & 7;
    const int n0 = blockIdx.x * 128;

    u64 acc[4][6];
    {
        const float4* bp = reinterpret_cast<const float4*>(b1 + 12 * c);
        float4 v0 = bp[0], v1 = bp[1], v2 = bp[2];
#pragma unroll
        for (int j = 0; j < 4; j++) {
            acc[j][0] = pack2f(v0.x, v0.y); acc[j][1] = pack2f(v0.z, v0.w);
            acc[j][2] = pack2f(v1.x, v1.y); acc[j][3] = pack2f(v1.z, v1.w);
            acc[j][4] = pack2f(v2.x, v2.y); acc[j][5] = pack2f(v2.z, v2.w);
        }
    }

    const float4* x4 = reinterpret_cast<const float4*>(x);
    const float4* a4 = g_aggr;
    const float4* w4 = reinterpret_cast<const float4*>(W1);
    float4* us4 = reinterpret_cast<float4*>(u_s);
    float4* ws4 = reinterpret_cast<float4*>(w_s);

    for (int kc = 0; kc < 3; kc++) {
        if (kc) __syncthreads();
#pragma unroll
        for (int j = 0; j < 4; j++) {
            int f4id = tid + 256 * j;
            int node = f4id >> 3, c4 = f4id & 7;
            int n = n0 + node;
            float4 v = make_float4(0.f, 0.f, 0.f, 0.f);
            if (n < N_NODES) {
                float4 xa = x4[(size_t)n * 24 + kc * 8 + c4];
                float4 ag = a4[(size_t)n * 24 + kc * 8 + c4];
                v = make_float4(xa.x + ag.x, xa.y + ag.y, xa.z + ag.z, xa.w + ag.w);
            }
            us4[f4id] = v;
        }
#pragma unroll
        for (int j = 0; j < 3; j++) ws4[tid + 256 * j] = w4[kc * 768 + tid + 256 * j];
        __syncthreads();

#pragma unroll 8
        for (int k = 0; k < 32; k++) {
            const ulonglong2* wp = reinterpret_cast<const ulonglong2*>(w_s + k * 96 + 12 * c);
            ulonglong2 q0 = wp[0], q1 = wp[1], q2 = wp[2];
#pragma unroll
            for (int j = 0; j < 4; j++) {
                u64 u = pack1(u_s[(r * 4 + j) * 32 + k]);
                acc[j][0] = fma2(q0.x, u, acc[j][0]);
                acc[j][1] = fma2(q0.y, u, acc[j][1]);
                acc[j][2] = fma2(q1.x, u, acc[j][2]);
                acc[j][3] = fma2(q1.y, u, acc[j][3]);
                acc[j][4] = fma2(q2.x, u, acc[j][4]);
                acc[j][5] = fma2(q2.y, u, acc[j][5]);
            }
        }
    }

    float4* h1 = g_h1;
#pragma unroll
    for (int j = 0; j < 4; j++) {
        int n = n0 + r * 4 + j;
        if (n < N_NODES) {
#pragma unroll
            for (int i = 0; i < 3; i++) {
                float a0, a1, a2, a3;
                unpack2(acc[j][2 * i], a0, a1);
                unpack2(acc[j][2 * i + 1], a2, a3);
                h1[(size_t)n * 24 + 3 * c + i] =
                    make_float4(fmaxf(a0, 0.f), fmaxf(a1, 0.f), fmaxf(a2, 0.f), fmaxf(a3, 0.f));
            }
        }
    }
}

// ---------------------------------------------------------------------------
// Kernel C2: h2 = h1 @ W2 + b2, with fused BN partial sums
// ---------------------------------------------------------------------------
__global__ void __launch_bounds__(256) mlp2_kernel(
    const float* __restrict__ W2,
    const float* __restrict__ b2)
{
    __shared__ __align__(16) float u_s[128 * 32];
    __shared__ __align__(16) float w_s[32 * 96];
    __shared__ float sSum[DIM];
    __shared__ float sSq[DIM];
    const int tid = threadIdx.x;
    const int r = tid >> 3, c = tid & 7;
    const int n0 = blockIdx.x * 128;
    if (tid < DIM) { sSum[tid] = 0.f; sSq[tid] = 0.f; }

    u64 acc[4][6];
    {
        const float4* bp = reinterpret_cast<const float4*>(b2 + 12 * c);
        float4 v0 = bp[0], v1 = bp[1], v2 = bp[2];
#pragma unroll
        for (int j = 0; j < 4; j++) {
            acc[j][0] = pack2f(v0.x, v0.y); acc[j][1] = pack2f(v0.z, v0.w);
            acc[j][2] = pack2f(v1.x, v1.y); acc[j][3] = pack2f(v1.z, v1.w);
            acc[j][4] = pack2f(v2.x, v2.y); acc[j][5] = pack2f(v2.z, v2.w);
        }
    }

    const float4* in4 = g_h1;
    const float4* w4 = reinterpret_cast<const float4*>(W2);
    float4* us4 = reinterpret_cast<float4*>(u_s);
    float4* ws4 = reinterpret_cast<float4*>(w_s);

    for (int kc = 0; kc < 3; kc++) {
        if (kc) __syncthreads();
#pragma unroll
        for (int j = 0; j < 4; j++) {
            int f4id = tid + 256 * j;
            int node = f4id >> 3, c4 = f4id & 7;
            int n = n0 + node;
            float4 v = make_float4(0.f, 0.f, 0.f, 0.f);
            if (n < N_NODES) v = in4[(size_t)n * 24 + kc * 8 + c4];
            us4[f4id] = v;
        }
#pragma unroll
        for (int j = 0; j < 3; j++) ws4[tid + 256 * j] = w4[kc * 768 + tid + 256 * j];
        __syncthreads();

#pragma unroll 8
        for (int k = 0; k < 32; k++) {
            const ulonglong2* wp = reinterpret_cast<const ulonglong2*>(w_s + k * 96 + 12 * c);
            ulonglong2 q0 = wp[0], q1 = wp[1], q2 = wp[2];
#pragma unroll
            for (int j = 0; j < 4; j++) {
                u64 u = pack1(u_s[(r * 4 + j) * 32 + k]);
                acc[j][0] = fma2(q0.x, u, acc[j][0]);
                acc[j][1] = fma2(q0.y, u, acc[j][1]);
                acc[j][2] = fma2(q1.x, u, acc[j][2]);
                acc[j][3] = fma2(q1.y, u, acc[j][3]);
                acc[j][4] = fma2(q2.x, u, acc[j][4]);
                acc[j][5] = fma2(q2.y, u, acc[j][5]);
            }
        }
    }

    float4* h2 = g_h2;
    float ps[12], pq[12];
#pragma unroll
    for (int t = 0; t < 12; t++) { ps[t] = 0.f; pq[t] = 0.f; }

#pragma unroll
    for (int j = 0; j < 4; j++) {
        int n = n0 + r * 4 + j;
        if (n < N_NODES) {
#pragma unroll
            for (int i = 0; i < 3; i++) {
                float a0, a1, a2, a3;
                unpack2(acc[j][2 * i], a0, a1);
                unpack2(acc[j][2 * i + 1], a2, a3);
                h2[(size_t)n * 24 + 3 * c + i] = make_float4(a0, a1, a2, a3);
                ps[4 * i + 0] += a0; pq[4 * i + 0] += a0 * a0;
                ps[4 * i + 1] += a1; pq[4 * i + 1] += a1 * a1;
                ps[4 * i + 2] += a2; pq[4 * i + 2] += a2 * a2;
                ps[4 * i + 3] += a3; pq[4 * i + 3] += a3 * a3;
            }
        }
    }
#pragma unroll
    for (int t = 0; t < 12; t++) {
        atomicAdd(&sSum[12 * c + t], ps[t]);
        atomicAdd(&sSq[12 * c + t], pq[t]);
    }
    __syncthreads();
    if (tid < DIM) {
        atomicAdd(&g_sum[tid], sSum[tid]);
        atomicAdd(&g_sumsq[tid], sSq[tid]);
    }
}

// ---------------------------------------------------------------------------
// Kernel D: BN scale/shift from stats
// ---------------------------------------------------------------------------
__global__ void bnstat_kernel(const float* __restrict__ gamma,
                              const float* __restrict__ beta)
{
    int f = threadIdx.x;
    if (f < DIM) {
        float mean = g_sum[f] * (1.f / N_NODES);
        float var = g_sumsq[f] * (1.f / N_NODES) - mean * mean;
        float sc = gamma[f] * rsqrtf(var + BN_EPS);
        g_scale[f] = sc;
        g_shift[f] = beta[f] - mean * sc;
    }
}

// ---------------------------------------------------------------------------
// Kernel E: out = relu(h2 * scale + shift)
// ---------------------------------------------------------------------------
__global__ void bn_apply_kernel(float* __restrict__ out)
{
    int i = blockIdx.x * blockDim.x + threadIdx.x;
    int stride = gridDim.x * blockDim.x;
    const int tot4 = N_NODES * DIM / 4;
    float4* out4 = reinterpret_cast<float4*>(out);
    for (int j = i; j < tot4; j += stride) {
        float4 v = g_h2[j];
        int f = (j * 4) % DIM;
        v.x = fmaxf(v.x * g_scale[f + 0] + g_shift[f + 0], 0.f);
        v.y = fmaxf(v.y * g_scale[f + 1] + g_shift[f + 1], 0.f);
        v.z = fmaxf(v.z * g_scale[f + 2] + g_shift[f + 2], 0.f);
        v.w = fmaxf(v.w * g_scale[f + 3] + g_shift[f + 3], 0.f);
        out4[j] = v;
    }
}

// ---------------------------------------------------------------------------
extern "C" void kernel_launch(void* const* d_in, const int* in_sizes, int n_in,
                              void* d_out, int out_size)
{
    const float* x     = (const float*)d_in[0];
    const int* ei      = (const int*)d_in[1];
    const float* ea    = (const float*)d_in[2];
    const float* We    = (const float*)d_in[3];
    const float* be    = (const float*)d_in[4];
    const float* W1    = (const float*)d_in[5];
    const float* b1    = (const float*)d_in[6];
    const float* W2    = (const float*)d_in[7];
    const float* b2    = (const float*)d_in[8];
    const float* gamma = (const float*)d_in[9];
    const float* beta  = (const float*)d_in[10];
    float* out         = (float*)d_out;

    zero_kernel<<<1184, 256>>>();
    edge_kernel<<<N_EDGES / 128, 256>>>(x, ei, ea, We, be);
    {
        const int nblocks = (N_NODES + 127) / 128;
        mlp1_kernel<<<nblocks, 256>>>(x, W1, b1);
        mlp2_kernel<<<nblocks, 256>>>(W2, b2);
    }
    bnstat_kernel<<<1, 128>>>(gamma, beta);
    bn_apply_kernel<<<1184, 256>>>(out);
}

// round 6
// speedup vs baseline: 2.4271x; 1.1169x over previous
#include <cuda_runtime.h>
#include <cstddef>
#include <cstdint>

#define N_NODES 50000
#define N_EDGES 800000
#define DIM 96
#define EDIM 32
#define BN_EPS 1e-5f

typedef unsigned long long u64;

// Scratch (__device__ globals per alloc-free rule)
__device__ float4 g_aggr[N_NODES * DIM / 4];
__device__ float4 g_h1[N_NODES * DIM / 4];
__device__ float4 g_h2[N_NODES * DIM / 4];
__device__ float g_sum[DIM];
__device__ float g_sumsq[DIM];
__device__ float g_scale[DIM];
__device__ float g_shift[DIM];

// ---- helpers --------------------------------------------------------------
__device__ __forceinline__ u64 fma2(u64 a, u64 b, u64 c) {
    u64 d;
    asm("fma.rn.f32x2 %0, %1, %2, %3;" : "=l"(d) : "l"(a), "l"(b), "l"(c));
    return d;
}
__device__ __forceinline__ u64 pack1(float x) {
    u64 r;
    asm("mov.b64 %0, {%1, %1};" : "=l"(r) : "f"(x));
    return r;
}
__device__ __forceinline__ u64 pack2f(float a, float b) {
    u64 r;
    asm("mov.b64 %0, {%1, %2};" : "=l"(r) : "f"(a), "f"(b));
    return r;
}
__device__ __forceinline__ void unpack2(u64 v, float& a, float& b) {
    asm("mov.b64 {%0, %1}, %2;" : "=f"(a), "=f"(b) : "l"(v));
}
__device__ __forceinline__ void red4(float* p, float a, float b, float c, float d) {
    asm volatile("red.global.add.v4.f32 [%0], {%1, %2, %3, %4};"
                 :: "l"(p), "f"(a), "f"(b), "f"(c), "f"(d) : "memory");
}
__device__ __forceinline__ uint32_t to_tf32(float f) {
    uint32_t r;
    asm("cvt.rna.tf32.f32 %0, %1;" : "=r"(r) : "f"(f));
    return r;
}
__device__ __forceinline__ void mma_tf32(float& d0, float& d1, float& d2, float& d3,
                                         uint32_t a0, uint32_t a1, uint32_t a2, uint32_t a3,
                                         uint32_t b0, uint32_t b1) {
    asm("mma.sync.aligned.m16n8k8.row.col.f32.tf32.tf32.f32 "
        "{%0,%1,%2,%3}, {%4,%5,%6,%7}, {%8,%9}, {%0,%1,%2,%3};"
        : "+f"(d0), "+f"(d1), "+f"(d2), "+f"(d3)
        : "r"(a0), "r"(a1), "r"(a2), "r"(a3), "r"(b0), "r"(b1));
}

// ---------------------------------------------------------------------------
// Kernel A: zero aggr + BN accumulators
// ---------------------------------------------------------------------------
__global__ void zero_kernel() {
    int i = blockIdx.x * blockDim.x + threadIdx.x;
    int stride = gridDim.x * blockDim.x;
    const float4 z4 = make_float4(0.f, 0.f, 0.f, 0.f);
    for (int j = i; j < N_NODES * DIM / 4; j += stride) g_aggr[j] = z4;
    if (i < DIM) { g_sum[i] = 0.f; g_sumsq[i] = 0.f; }
}

// ---------------------------------------------------------------------------
// Kernel B: tensor-core edge GEMM + fused scatter.
// Block = 64 edges, 128 threads (4 warps x 16 edges).
// proj = tf32_mma(ea, We); epilogue: relu(x[src]+proj+be) -> red.v4 aggr[dst].
// smem strides: ea 36 (A frags conflict-free), We 104 (B frags conflict-free),
// proj 100 (128-bit epilogue loads conflict-free per 8-lane phase).
// ---------------------------------------------------------------------------
#define EA_STRIDE 36
#define WE_STRIDE 104
#define PJ_STRIDE 100

__global__ void __launch_bounds__(128) edge_kernel(
    const float* __restrict__ x,
    const int* __restrict__ ei,        // [2, E]: row0=src, row1=dst
    const float* __restrict__ ea,      // [E, 32]
    const float* __restrict__ We,      // [32, 96]
    const float* __restrict__ be)      // [96]
{
    __shared__ __align__(16) uint32_t ea_s[64 * EA_STRIDE];   // 9216 B
    __shared__ __align__(16) uint32_t we_s[32 * WE_STRIDE];   // 13312 B
    __shared__ __align__(16) float pj_s[64 * PJ_STRIDE];      // 25600 B
    __shared__ __align__(16) float be_s[96];
    __shared__ int src_s[64];
    __shared__ int dst_s[64];

    const int tid = threadIdx.x;
    const int e0 = blockIdx.x * 64;

    // ---- fill smem (tf32 conversion on the fly) ----
    {
        const float4* eag = reinterpret_cast<const float4*>(ea) + (size_t)e0 * 8;
#pragma unroll
        for (int j = 0; j < 4; j++) {
            int idx = tid + 128 * j;           // 512 float4s total
            int edge = idx >> 3, kg = idx & 7;
            float4 v = eag[idx];
            uint32_t* p = ea_s + edge * EA_STRIDE + kg * 4;
            p[0] = to_tf32(v.x); p[1] = to_tf32(v.y);
            p[2] = to_tf32(v.z); p[3] = to_tf32(v.w);
        }
        const float4* wg = reinterpret_cast<const float4*>(We);
#pragma unroll
        for (int j = 0; j < 6; j++) {
            int idx = tid + 128 * j;           // 768 float4s total
            int k = idx / 24, n4 = idx % 24;
            float4 v = wg[idx];
            uint32_t* p = we_s + k * WE_STRIDE + n4 * 4;
            p[0] = to_tf32(v.x); p[1] = to_tf32(v.y);
            p[2] = to_tf32(v.z); p[3] = to_tf32(v.w);
        }
        if (tid < 96) be_s[tid] = be[tid];
        if (tid < 64) { src_s[tid] = ei[e0 + tid]; dst_s[tid] = ei[N_EDGES + e0 + tid]; }
    }
    __syncthreads();

    // ---- MMA phase: each warp computes 16 edges x 96 outs ----
    {
        const int lane = tid & 31, warp = tid >> 5;
        const int m0 = warp * 16;
        const int gr = lane >> 2, tg = lane & 3;

        uint32_t A[4][4];
#pragma unroll
        for (int ks = 0; ks < 4; ks++) {
            const uint32_t* ar0 = ea_s + (m0 + gr) * EA_STRIDE + ks * 8 + tg;
            const uint32_t* ar1 = ea_s + (m0 + gr + 8) * EA_STRIDE + ks * 8 + tg;
            A[ks][0] = ar0[0]; A[ks][1] = ar1[0];
            A[ks][2] = ar0[4]; A[ks][3] = ar1[4];
        }
#pragma unroll
        for (int nt = 0; nt < 12; nt++) {
            const int n0 = nt * 8;
            float d0 = 0.f, d1 = 0.f, d2 = 0.f, d3 = 0.f;
#pragma unroll
            for (int ks = 0; ks < 4; ks++) {
                uint32_t b0 = we_s[(ks * 8 + tg) * WE_STRIDE + n0 + gr];
                uint32_t b1 = we_s[(ks * 8 + tg + 4) * WE_STRIDE + n0 + gr];
                mma_tf32(d0, d1, d2, d3, A[ks][0], A[ks][1], A[ks][2], A[ks][3], b0, b1);
            }
            float2* q0 = reinterpret_cast<float2*>(pj_s + (m0 + gr) * PJ_STRIDE + n0 + 2 * tg);
            float2* q1 = reinterpret_cast<float2*>(pj_s + (m0 + gr + 8) * PJ_STRIDE + n0 + 2 * tg);
            *q0 = make_float2(d0, d1);
            *q1 = make_float2(d2, d3);
        }
    }
    __syncthreads();

    // ---- epilogue: relu(x[src] + proj + be), vectorized atomic scatter ----
    {
        const int c = tid & 7, r = tid >> 3;   // 8 col groups x 16 row groups
        const float4* bev = reinterpret_cast<const float4*>(be_s + 12 * c);
        float4 bv0 = bev[0], bv1 = bev[1], bv2 = bev[2];
        float* aggr = reinterpret_cast<float*>(g_aggr);
#pragma unroll
        for (int j = 0; j < 4; j++) {
            int el = r * 4 + j;
            int s = src_s[el], dv = dst_s[el];
            const float4* xr = reinterpret_cast<const float4*>(x + (size_t)s * DIM + 12 * c);
            const float4* pr = reinterpret_cast<const float4*>(pj_s + el * PJ_STRIDE + 12 * c);
            float* ar = aggr + (size_t)dv * DIM + 12 * c;
#pragma unroll
            for (int i = 0; i < 3; i++) {
                float4 p = pr[i];
                float4 xv = xr[i];
                float4 bb = (i == 0) ? bv0 : (i == 1) ? bv1 : bv2;
                float a0 = fmaxf(p.x + bb.x + xv.x, 0.f);
                float a1 = fmaxf(p.y + bb.y + xv.y, 0.f);
                float a2 = fmaxf(p.z + bb.z + xv.z, 0.f);
                float a3 = fmaxf(p.w + bb.w + xv.w, 0.f);
                red4(ar + 4 * i, a0, a1, a2, a3);
            }
        }
    }
}

// ---------------------------------------------------------------------------
// Kernel C1: h1 = relu((x + aggr) @ W1 + b1)   (unchanged, fp32 f32x2)
// ---------------------------------------------------------------------------
__global__ void __launch_bounds__(256) mlp1_kernel(
    const float* __restrict__ x,
    const float* __restrict__ W1,
    const float* __restrict__ b1)
{
    __shared__ __align__(16) float u_s[128 * 32];
    __shared__ __align__(16) float w_s[32 * 96];
    const int tid = threadIdx.x;
    const int r = tid >> 3, c = tid & 7;
    const int n0 = blockIdx.x * 128;

    u64 acc[4][6];
    {
        const float4* bp = reinterpret_cast<const float4*>(b1 + 12 * c);
        float4 v0 = bp[0], v1 = bp[1], v2 = bp[2];
#pragma unroll
        for (int j = 0; j < 4; j++) {
            acc[j][0] = pack2f(v0.x, v0.y); acc[j][1] = pack2f(v0.z, v0.w);
            acc[j][2] = pack2f(v1.x, v1.y); acc[j][3] = pack2f(v1.z, v1.w);
            acc[j][4] = pack2f(v2.x, v2.y); acc[j][5] = pack2f(v2.z, v2.w);
        }
    }

    const float4* x4 = reinterpret_cast<const float4*>(x);
    const float4* a4 = g_aggr;
    const float4* w4 = reinterpret_cast<const float4*>(W1);
    float4* us4 = reinterpret_cast<float4*>(u_s);
    float4* ws4 = reinterpret_cast<float4*>(w_s);

    for (int kc = 0; kc < 3; kc++) {
        if (kc) __syncthreads();
#pragma unroll
        for (int j = 0; j < 4; j++) {
            int f4id = tid + 256 * j;
            int node = f4id >> 3, c4 = f4id & 7;
            int n = n0 + node;
            float4 v = make_float4(0.f, 0.f, 0.f, 0.f);
            if (n < N_NODES) {
                float4 xa = x4[(size_t)n * 24 + kc * 8 + c4];
                float4 ag = a4[(size_t)n * 24 + kc * 8 + c4];
                v = make_float4(xa.x + ag.x, xa.y + ag.y, xa.z + ag.z, xa.w + ag.w);
            }
            us4[f4id] = v;
        }
#pragma unroll
        for (int j = 0; j < 3; j++) ws4[tid + 256 * j] = w4[kc * 768 + tid + 256 * j];
        __syncthreads();

#pragma unroll 8
        for (int k = 0; k < 32; k++) {
            const ulonglong2* wp = reinterpret_cast<const ulonglong2*>(w_s + k * 96 + 12 * c);
            ulonglong2 q0 = wp[0], q1 = wp[1], q2 = wp[2];
#pragma unroll
            for (int j = 0; j < 4; j++) {
                u64 u = pack1(u_s[(r * 4 + j) * 32 + k]);
                acc[j][0] = fma2(q0.x, u, acc[j][0]);
                acc[j][1] = fma2(q0.y, u, acc[j][1]);
                acc[j][2] = fma2(q1.x, u, acc[j][2]);
                acc[j][3] = fma2(q1.y, u, acc[j][3]);
                acc[j][4] = fma2(q2.x, u, acc[j][4]);
                acc[j][5] = fma2(q2.y, u, acc[j][5]);
            }
        }
    }

    float4* h1 = g_h1;
#pragma unroll
    for (int j = 0; j < 4; j++) {
        int n = n0 + r * 4 + j;
        if (n < N_NODES) {
#pragma unroll
            for (int i = 0; i < 3; i++) {
                float a0, a1, a2, a3;
                unpack2(acc[j][2 * i], a0, a1);
                unpack2(acc[j][2 * i + 1], a2, a3);
                h1[(size_t)n * 24 + 3 * c + i] =
                    make_float4(fmaxf(a0, 0.f), fmaxf(a1, 0.f), fmaxf(a2, 0.f), fmaxf(a3, 0.f));
            }
        }
    }
}

// ---------------------------------------------------------------------------
// Kernel C2: h2 = h1 @ W2 + b2, fused BN partial sums (unchanged)
// ---------------------------------------------------------------------------
__global__ void __launch_bounds__(256) mlp2_kernel(
    const float* __restrict__ W2,
    const float* __restrict__ b2)
{
    __shared__ __align__(16) float u_s[128 * 32];
    __shared__ __align__(16) float w_s[32 * 96];
    __shared__ float sSum[DIM];
    __shared__ float sSq[DIM];
    const int tid = threadIdx.x;
    const int r = tid >> 3, c = tid & 7;
    const int n0 = blockIdx.x * 128;
    if (tid < DIM) { sSum[tid] = 0.f; sSq[tid] = 0.f; }

    u64 acc[4][6];
    {
        const float4* bp = reinterpret_cast<const float4*>(b2 + 12 * c);
        float4 v0 = bp[0], v1 = bp[1], v2 = bp[2];
#pragma unroll
        for (int j = 0; j < 4; j++) {
            acc[j][0] = pack2f(v0.x, v0.y); acc[j][1] = pack2f(v0.z, v0.w);
            acc[j][2] = pack2f(v1.x, v1.y); acc[j][3] = pack2f(v1.z, v1.w);
            acc[j][4] = pack2f(v2.x, v2.y); acc[j][5] = pack2f(v2.z, v2.w);
        }
    }

    const float4* in4 = g_h1;
    const float4* w4 = reinterpret_cast<const float4*>(W2);
    float4* us4 = reinterpret_cast<float4*>(u_s);
    float4* ws4 = reinterpret_cast<float4*>(w_s);

    for (int kc = 0; kc < 3; kc++) {
        if (kc) __syncthreads();
#pragma unroll
        for (int j = 0; j < 4; j++) {
            int f4id = tid + 256 * j;
            int node = f4id >> 3, c4 = f4id & 7;
            int n = n0 + node;
            float4 v = make_float4(0.f, 0.f, 0.f, 0.f);
            if (n < N_NODES) v = in4[(size_t)n * 24 + kc * 8 + c4];
            us4[f4id] = v;
        }
#pragma unroll
        for (int j = 0; j < 3; j++) ws4[tid + 256 * j] = w4[kc * 768 + tid + 256 * j];
        __syncthreads();

#pragma unroll 8
        for (int k = 0; k < 32; k++) {
            const ulonglong2* wp = reinterpret_cast<const ulonglong2*>(w_s + k * 96 + 12 * c);
            ulonglong2 q0 = wp[0], q1 = wp[1], q2 = wp[2];
#pragma unroll
            for (int j = 0; j < 4; j++) {
                u64 u = pack1(u_s[(r * 4 + j) * 32 + k]);
                acc[j][0] = fma2(q0.x, u, acc[j][0]);
                acc[j][1] = fma2(q0.y, u, acc[j][1]);
                acc[j][2] = fma2(q1.x, u, acc[j][2]);
                acc[j][3] = fma2(q1.y, u, acc[j][3]);
                acc[j][4] = fma2(q2.x, u, acc[j][4]);
                acc[j][5] = fma2(q2.y, u, acc[j][5]);
            }
        }
    }

    float4* h2 = g_h2;
    float ps[12], pq[12];
#pragma unroll
    for (int t = 0; t < 12; t++) { ps[t] = 0.f; pq[t] = 0.f; }

#pragma unroll
    for (int j = 0; j < 4; j++) {
        int n = n0 + r * 4 + j;
        if (n < N_NODES) {
#pragma unroll
            for (int i = 0; i < 3; i++) {
                float a0, a1, a2, a3;
                unpack2(acc[j][2 * i], a0, a1);
                unpack2(acc[j][2 * i + 1], a2, a3);
                h2[(size_t)n * 24 + 3 * c + i] = make_float4(a0, a1, a2, a3);
                ps[4 * i + 0] += a0; pq[4 * i + 0] += a0 * a0;
                ps[4 * i + 1] += a1; pq[4 * i + 1] += a1 * a1;
                ps[4 * i + 2] += a2; pq[4 * i + 2] += a2 * a2;
                ps[4 * i + 3] += a3; pq[4 * i + 3] += a3 * a3;
            }
        }
    }
#pragma unroll
    for (int t = 0; t < 12; t++) {
        atomicAdd(&sSum[12 * c + t], ps[t]);
        atomicAdd(&sSq[12 * c + t], pq[t]);
    }
    __syncthreads();
    if (tid < DIM) {
        atomicAdd(&g_sum[tid], sSum[tid]);
        atomicAdd(&g_sumsq[tid], sSq[tid]);
    }
}

// ---------------------------------------------------------------------------
// Kernel D: BN scale/shift from stats
// ---------------------------------------------------------------------------
__global__ void bnstat_kernel(const float* __restrict__ gamma,
                              const float* __restrict__ beta)
{
    int f = threadIdx.x;
    if (f < DIM) {
        float mean = g_sum[f] * (1.f / N_NODES);
        float var = g_sumsq[f] * (1.f / N_NODES) - mean * mean;
        float sc = gamma[f] * rsqrtf(var + BN_EPS);
        g_scale[f] = sc;
        g_shift[f] = beta[f] - mean * sc;
    }
}

// ---------------------------------------------------------------------------
// Kernel E: out = relu(h2 * scale + shift)
// ---------------------------------------------------------------------------
__global__ void bn_apply_kernel(float* __restrict__ out)
{
    int i = blockIdx.x * blockDim.x + threadIdx.x;
    int stride = gridDim.x * blockDim.x;
    const int tot4 = N_NODES * DIM / 4;
    float4* out4 = reinterpret_cast<float4*>(out);
    for (int j = i; j < tot4; j += stride) {
        float4 v = g_h2[j];
        int f = (j * 4) % DIM;
        v.x = fmaxf(v.x * g_scale[f + 0] + g_shift[f + 0], 0.f);
        v.y = fmaxf(v.y * g_scale[f + 1] + g_shift[f + 1], 0.f);
        v.z = fmaxf(v.z * g_scale[f + 2] + g_shift[f + 2], 0.f);
        v.w = fmaxf(v.w * g_scale[f + 3] + g_shift[f + 3], 0.f);
        out4[j] = v;
    }
}

// ---------------------------------------------------------------------------
extern "C" void kernel_launch(void* const* d_in, const int* in_sizes, int n_in,
                              void* d_out, int out_size)
{
    const float* x     = (const float*)d_in[0];
    const int* ei      = (const int*)d_in[1];
    const float* ea    = (const float*)d_in[2];
    const float* We    = (const float*)d_in[3];
    const float* be    = (const float*)d_in[4];
    const float* W1    = (const float*)d_in[5];
    const float* b1    = (const float*)d_in[6];
    const float* W2    = (const float*)d_in[7];
    const float* b2    = (const float*)d_in[8];
    const float* gamma = (const float*)d_in[9];
    const float* beta  = (const float*)d_in[10];
    float* out         = (float*)d_out;

    zero_kernel<<<1184, 256>>>();
    edge_kernel<<<N_EDGES / 64, 128>>>(x, ei, ea, We, be);
    {
        const int nblocks = (N_NODES + 127) / 128;
        mlp1_kernel<<<nblocks, 256>>>(x, W1, b1);
        mlp2_kernel<<<nblocks, 256>>>(W2, b2);
    }
    bnstat_kernel<<<1, 128>>>(gamma, beta);
    bn_apply_kernel<<<1184, 256>>>(out);
}

// round 9
// speedup vs baseline: 2.8015x; 1.1543x over previous
#include <cuda_runtime.h>
#include <cstddef>
#include <cstdint>

#define N_NODES 50000
#define N_EDGES 800000
#define DIM 96
#define EDIM 32
#define BN_EPS 1e-5f

typedef unsigned long long u64;

// Scratch (__device__ globals per alloc-free rule)
__device__ float4 g_aggr[N_NODES * DIM / 4];
__device__ float4 g_h2[N_NODES * DIM / 4];
__device__ float g_sum[DIM];
__device__ float g_sumsq[DIM];
__device__ float g_scale[DIM];
__device__ float g_shift[DIM];

// ---- helpers --------------------------------------------------------------
__device__ __forceinline__ void red4(float* p, float a, float b, float c, float d) {
    asm volatile("red.global.add.v4.f32 [%0], {%1, %2, %3, %4};"
                 :: "l"(p), "f"(a), "f"(b), "f"(c), "f"(d) : "memory");
}
__device__ __forceinline__ uint32_t to_tf32(float f) {
    uint32_t r;
    asm("cvt.rna.tf32.f32 %0, %1;" : "=r"(r) : "f"(f));
    return r;
}
__device__ __forceinline__ void mma_tf32(float& d0, float& d1, float& d2, float& d3,
                                         uint32_t a0, uint32_t a1, uint32_t a2, uint32_t a3,
                                         uint32_t b0, uint32_t b1) {
    asm("mma.sync.aligned.m16n8k8.row.col.f32.tf32.tf32.f32 "
        "{%0,%1,%2,%3}, {%4,%5,%6,%7}, {%8,%9}, {%0,%1,%2,%3};"
        : "+f"(d0), "+f"(d1), "+f"(d2), "+f"(d3)
        : "r"(a0), "r"(a1), "r"(a2), "r"(a3), "r"(b0), "r"(b1));
}
__device__ __forceinline__ uint4 tf32x4(float4 v) {
    uint4 t;
    t.x = to_tf32(v.x); t.y = to_tf32(v.y); t.z = to_tf32(v.z); t.w = to_tf32(v.w);
    return t;
}

// ---------------------------------------------------------------------------
// Kernel A: zero aggr + BN accumulators
// ---------------------------------------------------------------------------
__global__ void zero_kernel() {
    int i = blockIdx.x * blockDim.x + threadIdx.x;
    int stride = gridDim.x * blockDim.x;
    const float4 z4 = make_float4(0.f, 0.f, 0.f, 0.f);
    for (int j = i; j < N_NODES * DIM / 4; j += stride) g_aggr[j] = z4;
    if (i < DIM) { g_sum[i] = 0.f; g_sumsq[i] = 0.f; }
}

// ---------------------------------------------------------------------------
// Kernel B: tensor-core edge GEMM + fused scatter (unchanged from R6).
// ---------------------------------------------------------------------------
#define EA_STRIDE 36
#define WE_STRIDE 104
#define PJ_STRIDE 100

__global__ void __launch_bounds__(128) edge_kernel(
    const float* __restrict__ x,
    const int* __restrict__ ei,        // [2, E]: row0=src, row1=dst
    const float* __restrict__ ea,      // [E, 32]
    const float* __restrict__ We,      // [32, 96]
    const float* __restrict__ be)      // [96]
{
    __shared__ __align__(16) uint32_t ea_s[64 * EA_STRIDE];
    __shared__ __align__(16) uint32_t we_s[32 * WE_STRIDE];
    __shared__ __align__(16) float pj_s[64 * PJ_STRIDE];
    __shared__ __align__(16) float be_s[96];
    __shared__ int src_s[64];
    __shared__ int dst_s[64];

    const int tid = threadIdx.x;
    const int e0 = blockIdx.x * 64;

    {
        const float4* eag = reinterpret_cast<const float4*>(ea) + (size_t)e0 * 8;
#pragma unroll
        for (int j = 0; j < 4; j++) {
            int idx = tid + 128 * j;
            int edge = idx >> 3, kg = idx & 7;
            float4 v = eag[idx];
            uint32_t* p = ea_s + edge * EA_STRIDE + kg * 4;
            p[0] = to_tf32(v.x); p[1] = to_tf32(v.y);
            p[2] = to_tf32(v.z); p[3] = to_tf32(v.w);
        }
        const float4* wg = reinterpret_cast<const float4*>(We);
#pragma unroll
        for (int j = 0; j < 6; j++) {
            int idx = tid + 128 * j;
            int k = idx / 24, n4 = idx % 24;
            float4 v = wg[idx];
            uint32_t* p = we_s + k * WE_STRIDE + n4 * 4;
            p[0] = to_tf32(v.x); p[1] = to_tf32(v.y);
            p[2] = to_tf32(v.z); p[3] = to_tf32(v.w);
        }
        if (tid < 96) be_s[tid] = be[tid];
        if (tid < 64) { src_s[tid] = ei[e0 + tid]; dst_s[tid] = ei[N_EDGES + e0 + tid]; }
    }
    __syncthreads();

    {
        const int lane = tid & 31, warp = tid >> 5;
        const int m0 = warp * 16;
        const int gr = lane >> 2, tg = lane & 3;

        uint32_t A[4][4];
#pragma unroll
        for (int ks = 0; ks < 4; ks++) {
            const uint32_t* ar0 = ea_s + (m0 + gr) * EA_STRIDE + ks * 8 + tg;
            const uint32_t* ar1 = ea_s + (m0 + gr + 8) * EA_STRIDE + ks * 8 + tg;
            A[ks][0] = ar0[0]; A[ks][1] = ar1[0];
            A[ks][2] = ar0[4]; A[ks][3] = ar1[4];
        }
#pragma unroll
        for (int nt = 0; nt < 12; nt++) {
            const int n0 = nt * 8;
            float d0 = 0.f, d1 = 0.f, d2 = 0.f, d3 = 0.f;
#pragma unroll
            for (int ks = 0; ks < 4; ks++) {
                uint32_t b0 = we_s[(ks * 8 + tg) * WE_STRIDE + n0 + gr];
                uint32_t b1 = we_s[(ks * 8 + tg + 4) * WE_STRIDE + n0 + gr];
                mma_tf32(d0, d1, d2, d3, A[ks][0], A[ks][1], A[ks][2], A[ks][3], b0, b1);
            }
            float2* q0 = reinterpret_cast<float2*>(pj_s + (m0 + gr) * PJ_STRIDE + n0 + 2 * tg);
            float2* q1 = reinterpret_cast<float2*>(pj_s + (m0 + gr + 8) * PJ_STRIDE + n0 + 2 * tg);
            *q0 = make_float2(d0, d1);
            *q1 = make_float2(d2, d3);
        }
    }
    __syncthreads();

    {
        const int c = tid & 7, r = tid >> 3;
        const float4* bev = reinterpret_cast<const float4*>(be_s + 12 * c);
        float4 bv0 = bev[0], bv1 = bev[1], bv2 = bev[2];
        float* aggr = reinterpret_cast<float*>(g_aggr);
#pragma unroll
        for (int j = 0; j < 4; j++) {
            int el = r * 4 + j;
            int s = src_s[el], dv = dst_s[el];
            const float4* xr = reinterpret_cast<const float4*>(x + (size_t)s * DIM + 12 * c);
            const float4* pr = reinterpret_cast<const float4*>(pj_s + el * PJ_STRIDE + 12 * c);
            float* ar = aggr + (size_t)dv * DIM + 12 * c;
#pragma unroll
            for (int i = 0; i < 3; i++) {
                float4 p = pr[i];
                float4 xv = xr[i];
                float4 bb = (i == 0) ? bv0 : (i == 1) ? bv1 : bv2;
                float a0 = fmaxf(p.x + bb.x + xv.x, 0.f);
                float a1 = fmaxf(p.y + bb.y + xv.y, 0.f);
                float a2 = fmaxf(p.z + bb.z + xv.z, 0.f);
                float a3 = fmaxf(p.w + bb.w + xv.w, 0.f);
                red4(ar + 4 * i, a0, a1, a2, a3);
            }
        }
    }
}

// ---------------------------------------------------------------------------
// Kernel C: FUSED MLP  h2 = relu((x+aggr)@W1 + b1) @ W2 + b2  (tf32 mma)
// Block = 64 nodes, 128 threads (4 warps x 16 rows). h1 never leaves smem.
// u_s stride 100: A-fragment loads conflict-free; w_s stride 100 likewise.
// ---------------------------------------------------------------------------
#define US 100
__global__ void __launch_bounds__(128) mlp_fused_kernel(
    const float* __restrict__ x,
    const float* __restrict__ W1,
    const float* __restrict__ pb1,
    const float* __restrict__ W2,
    const float* __restrict__ pb2)
{
    __shared__ __align__(16) uint32_t u_s[64 * US];   // 25600 B (A tf32, then h1 tf32)
    __shared__ __align__(16) uint32_t w_s[32 * US];   // 12800 B (W k-chunk tf32)
    __shared__ float b1_s[96], b2_s[96];

    const int tid = threadIdx.x;
    const int lane = tid & 31, warp = tid >> 5;
    const int gr = lane >> 2, tg = lane & 3;
    const int m0 = warp * 16;
    const int n0b = blockIdx.x * 64;

    if (tid < 96) { b1_s[tid] = pb1[tid]; b2_s[tid] = pb2[tid]; }

    // ---- fill u_s = tf32(x + aggr) ----
    {
        const float4* x4 = reinterpret_cast<const float4*>(x);
        const float4* a4 = g_aggr;
#pragma unroll
        for (int j = 0; j < 12; j++) {
            int idx = tid + 128 * j;          // 1536 float4s
            int node = idx / 24, c4 = idx % 24;
            int n = n0b + node;
            float4 v = make_float4(0.f, 0.f, 0.f, 0.f);
            if (n < N_NODES) {
                float4 xa = x4[(size_t)n * 24 + c4];
                float4 ag = a4[(size_t)n * 24 + c4];
                v = make_float4(xa.x + ag.x, xa.y + ag.y, xa.z + ag.z, xa.w + ag.w);
            }
            *reinterpret_cast<uint4*>(u_s + node * US + c4 * 4) = tf32x4(v);
        }
    }
    __syncthreads();

    uint32_t A[12][4];
    float acc[12][4];

    // ---- load stage-1 A fragments ----
#pragma unroll
    for (int ks = 0; ks < 12; ks++) {
        const uint32_t* r0 = u_s + (m0 + gr) * US + ks * 8 + tg;
        const uint32_t* r1 = u_s + (m0 + gr + 8) * US + ks * 8 + tg;
        A[ks][0] = r0[0]; A[ks][1] = r1[0]; A[ks][2] = r0[4]; A[ks][3] = r1[4];
    }
#pragma unroll
    for (int nt = 0; nt < 12; nt++)
#pragma unroll
        for (int i = 0; i < 4; i++) acc[nt][i] = 0.f;

    // ---- stage 1 GEMM: (x+aggr) @ W1 ----
    const float4* w14 = reinterpret_cast<const float4*>(W1);
    for (int kc = 0; kc < 3; kc++) {
#pragma unroll
        for (int j = 0; j < 6; j++) {
            int idx = tid + 128 * j;          // 768 float4s
            int r = idx / 24, c4 = idx % 24;
            *reinterpret_cast<uint4*>(w_s + r * US + c4 * 4) =
                tf32x4(w14[(size_t)(kc * 32 + r) * 24 + c4]);
        }
        __syncthreads();
#pragma unroll
        for (int nt = 0; nt < 12; nt++) {
            const int n0 = nt * 8;
#pragma unroll
            for (int ks4 = 0; ks4 < 4; ks4++) {
                uint32_t b0 = w_s[(ks4 * 8 + tg) * US + n0 + gr];
                uint32_t b1v = w_s[(ks4 * 8 + tg + 4) * US + n0 + gr];
                const int ks = kc * 4 + ks4;
                mma_tf32(acc[nt][0], acc[nt][1], acc[nt][2], acc[nt][3],
                         A[ks][0], A[ks][1], A[ks][2], A[ks][3], b0, b1v);
            }
        }
        __syncthreads();
    }

    // ---- stage-1 epilogue: h1 = relu(acc + b1) -> u_s (tf32) ----
#pragma unroll
    for (int nt = 0; nt < 12; nt++) {
        const int c0 = nt * 8 + 2 * tg;
        float h00 = fmaxf(acc[nt][0] + b1_s[c0], 0.f);
        float h01 = fmaxf(acc[nt][1] + b1_s[c0 + 1], 0.f);
        float h10 = fmaxf(acc[nt][2] + b1_s[c0], 0.f);
        float h11 = fmaxf(acc[nt][3] + b1_s[c0 + 1], 0.f);
        uint2 v0 = make_uint2(to_tf32(h00), to_tf32(h01));
        uint2 v1 = make_uint2(to_tf32(h10), to_tf32(h11));
        *reinterpret_cast<uint2*>(u_s + (m0 + gr) * US + c0) = v0;
        *reinterpret_cast<uint2*>(u_s + (m0 + gr + 8) * US + c0) = v1;
#pragma unroll
        for (int i = 0; i < 4; i++) acc[nt][i] = 0.f;
    }
    __syncthreads();

    // ---- load stage-2 A fragments (h1) ----
#pragma unroll
    for (int ks = 0; ks < 12; ks++) {
        const uint32_t* r0 = u_s + (m0 + gr) * US + ks * 8 + tg;
        const uint32_t* r1 = u_s + (m0 + gr + 8) * US + ks * 8 + tg;
        A[ks][0] = r0[0]; A[ks][1] = r1[0]; A[ks][2] = r0[4]; A[ks][3] = r1[4];
    }

    // ---- stage 2 GEMM: h1 @ W2 ----
    const float4* w24 = reinterpret_cast<const float4*>(W2);
    for (int kc = 0; kc < 3; kc++) {
        __syncthreads();
#pragma unroll
        for (int j = 0; j < 6; j++) {
            int idx = tid + 128 * j;
            int r = idx / 24, c4 = idx % 24;
            *reinterpret_cast<uint4*>(w_s + r * US + c4 * 4) =
                tf32x4(w24[(size_t)(kc * 32 + r) * 24 + c4]);
        }
        __syncthreads();
#pragma unroll
        for (int nt = 0; nt < 12; nt++) {
            const int n0 = nt * 8;
#pragma unroll
            for (int ks4 = 0; ks4 < 4; ks4++) {
                uint32_t b0 = w_s[(ks4 * 8 + tg) * US + n0 + gr];
                uint32_t b1v = w_s[(ks4 * 8 + tg + 4) * US + n0 + gr];
                const int ks = kc * 4 + ks4;
                mma_tf32(acc[nt][0], acc[nt][1], acc[nt][2], acc[nt][3],
                         A[ks][0], A[ks][1], A[ks][2], A[ks][3], b0, b1v);
            }
        }
    }

    // ---- stage-2 epilogue: h2 = acc + b2 -> g_h2 ----
    {
        float2* h2f2 = reinterpret_cast<float2*>(g_h2);
        const int row0 = n0b + m0 + gr;
        const int row1 = row0 + 8;
#pragma unroll
        for (int nt = 0; nt < 12; nt++) {
            const int c0 = nt * 8 + 2 * tg;
            if (row0 < N_NODES)
                h2f2[(size_t)row0 * 48 + c0 / 2] =
                    make_float2(acc[nt][0] + b2_s[c0], acc[nt][1] + b2_s[c0 + 1]);
            if (row1 < N_NODES)
                h2f2[(size_t)row1 * 48 + c0 / 2] =
                    make_float2(acc[nt][2] + b2_s[c0], acc[nt][3] + b2_s[c0 + 1]);
        }
    }
}

// ---------------------------------------------------------------------------
// Kernel C2: BN partial sums over g_h2 (192 threads = 8 rows x 24 col-quads)
// ---------------------------------------------------------------------------
__global__ void __launch_bounds__(192) bnsum_kernel() {
    __shared__ float sS[DIM], sQ[DIM];
    const int t = threadIdx.x;
    const int c4 = t % 24, rt = t / 24;
    if (t < DIM) { sS[t] = 0.f; sQ[t] = 0.f; }
    __syncthreads();

    float4 ps = make_float4(0.f, 0.f, 0.f, 0.f);
    float4 pq = make_float4(0.f, 0.f, 0.f, 0.f);
    for (int r = blockIdx.x * 8 + rt; r < N_NODES; r += gridDim.x * 8) {
        float4 v = g_h2[(size_t)r * 24 + c4];
        ps.x += v.x; ps.y += v.y; ps.z += v.z; ps.w += v.w;
        pq.x += v.x * v.x; pq.y += v.y * v.y; pq.z += v.z * v.z; pq.w += v.w * v.w;
    }
    atomicAdd(&sS[c4 * 4 + 0], ps.x); atomicAdd(&sQ[c4 * 4 + 0], pq.x);
    atomicAdd(&sS[c4 * 4 + 1], ps.y); atomicAdd(&sQ[c4 * 4 + 1], pq.y);
    atomicAdd(&sS[c4 * 4 + 2], ps.z); atomicAdd(&sQ[c4 * 4 + 2], pq.z);
    atomicAdd(&sS[c4 * 4 + 3], ps.w); atomicAdd(&sQ[c4 * 4 + 3], pq.w);
    __syncthreads();
    if (t < DIM) {
        atomicAdd(&g_sum[t], sS[t]);
        atomicAdd(&g_sumsq[t], sQ[t]);
    }
}

// ---------------------------------------------------------------------------
// Kernel D: BN scale/shift from stats
// ---------------------------------------------------------------------------
__global__ void bnstat_kernel(const float* __restrict__ gamma,
                              const float* __restrict__ beta)
{
    int f = threadIdx.x;
    if (f < DIM) {
        float mean = g_sum[f] * (1.f / N_NODES);
        float var = g_sumsq[f] * (1.f / N_NODES) - mean * mean;
        float sc = gamma[f] * rsqrtf(var + BN_EPS);
        g_scale[f] = sc;
        g_shift[f] = beta[f] - mean * sc;
    }
}

// ---------------------------------------------------------------------------
// Kernel E: out = relu(h2 * scale + shift)
// ---------------------------------------------------------------------------
__global__ void bn_apply_kernel(float* __restrict__ out)
{
    int i = blockIdx.x * blockDim.x + threadIdx.x;
    int stride = gridDim.x * blockDim.x;
    const int tot4 = N_NODES * DIM / 4;
    float4* out4 = reinterpret_cast<float4*>(out);
    for (int j = i; j < tot4; j += stride) {
        float4 v = g_h2[j];
        int f = (j * 4) % DIM;
        v.x = fmaxf(v.x * g_scale[f + 0] + g_shift[f + 0], 0.f);
        v.y = fmaxf(v.y * g_scale[f + 1] + g_shift[f + 1], 0.f);
        v.z = fmaxf(v.z * g_scale[f + 2] + g_shift[f + 2], 0.f);
        v.w = fmaxf(v.w * g_scale[f + 3] + g_shift[f + 3], 0.f);
        out4[j] = v;
    }
}

// ---------------------------------------------------------------------------
extern "C" void kernel_launch(void* const* d_in, const int* in_sizes, int n_in,
                              void* d_out, int out_size)
{
    const float* x     = (const float*)d_in[0];
    const int* ei      = (const int*)d_in[1];
    const float* ea    = (const float*)d_in[2];
    const float* We    = (const float*)d_in[3];
    const float* be    = (const float*)d_in[4];
    const float* W1    = (const float*)d_in[5];
    const float* b1    = (const float*)d_in[6];
    const float* W2    = (const float*)d_in[7];
    const float* b2    = (const float*)d_in[8];
    const float* gamma = (const float*)d_in[9];
    const float* beta  = (const float*)d_in[10];
    float* out         = (float*)d_out;

    zero_kernel<<<1184, 256>>>();
    edge_kernel<<<N_EDGES / 64, 128>>>(x, ei, ea, We, be);
    mlp_fused_kernel<<<(N_NODES + 63) / 64, 128>>>(x, W1, b1, W2, b2);
    bnsum_kernel<<<208, 192>>>();
    bnstat_kernel<<<1, 128>>>(gamma, beta);
    bn_apply_kernel<<<1184, 256>>>(out);
}